// round 14
// baseline (speedup 1.0000x reference)
#include <cuda_runtime.h>
#include <cuda_fp16.h>
#include <cstdint>
#include <math.h>

#define NNODES 262144
#define KNBR 8

// ---------------- global scratch (allocation-free) ----------------
__device__ __half g_h1[(size_t)NNODES * 128];   // fp16 intermediate
__device__ __half g_z[(size_t)NNODES * 128];    // Z = h2 @ Wcat2 (fp16, L2-resident)
__device__ float  g_invd[(size_t)NNODES * KNBR];
__device__ __half g_wt0h[128 * 128];            // W0^T [N,K] fp16
__device__ __half g_wt1h[128 * 1024];           // W1^T [N,K] fp16
__device__ __half g_wt2c[128 * 128];            // Wcat2^T [c=k*16+j][f] fp16

// ---------------- helpers ----------------
__device__ __forceinline__ uint32_t smem_u32(const void* p) {
    uint32_t a;
    asm("{ .reg .u64 t; cvta.to.shared.u64 t, %1; cvt.u32.u64 %0, t; }"
        : "=r"(a) : "l"(p));
    return a;
}
__device__ __forceinline__ uint32_t swz128(uint32_t off) {
    return off ^ ((off >> 3) & 0x70);
}
__device__ __forceinline__ void ldsm4(uint32_t* r, uint32_t addr) {
    asm volatile("ldmatrix.sync.aligned.m8n8.x4.shared.b16 {%0,%1,%2,%3}, [%4];"
                 : "=r"(r[0]), "=r"(r[1]), "=r"(r[2]), "=r"(r[3]) : "r"(addr));
}
__device__ __forceinline__ void mma16816(float* d, const uint32_t* a,
                                         uint32_t b0, uint32_t b1) {
    asm volatile(
        "mma.sync.aligned.m16n8k16.row.col.f32.f16.f16.f32 "
        "{%0,%1,%2,%3}, {%4,%5,%6,%7}, {%8,%9}, {%0,%1,%2,%3};"
        : "+f"(d[0]), "+f"(d[1]), "+f"(d[2]), "+f"(d[3])
        : "r"(a[0]), "r"(a[1]), "r"(a[2]), "r"(a[3]), "r"(b0), "r"(b1));
}
__device__ __forceinline__ uint32_t pack_h2(float a, float b) {
    uint32_t d;
    asm("cvt.rn.f16x2.f32 %0, %1, %2;" : "=r"(d) : "f"(b), "f"(a));
    return d;
}
__device__ __forceinline__ void cp_async16(uint32_t dst, const void* src) {
    asm volatile("cp.async.cg.shared.global [%0], [%1], 16;"
                 :: "r"(dst), "l"(src));
}
// store with L2 evict_last policy (keep Z resident for combine2)
__device__ __forceinline__ void stg_b32_evict_last(void* ptr, uint32_t val,
                                                   uint64_t pol) {
    asm volatile("st.global.L2::cache_hint.b32 [%0], %1, %2;"
                 :: "l"(ptr), "r"(val), "l"(pol) : "memory");
}

// ---------------- merged prep kernel ----------------
// blocks [0,8192): invdist; [8192,8256): W0^T; [8256,8768): W1^T; [8768,8832): Wcat2
__global__ void __launch_bounds__(256)
prep_kernel(const float* __restrict__ pos, const int* __restrict__ nbr,
            const float* __restrict__ W0, const float* __restrict__ W1,
            const float* __restrict__ W2) {
    int b = blockIdx.x, tid = threadIdx.x;
    if (b < 8192) {
        int i = b * 256 + tid;
        int n = i >> 3;
        int j = nbr[i];
        float dx = pos[3 * n + 0] - pos[3 * j + 0];
        float dy = pos[3 * n + 1] - pos[3 * j + 1];
        float dz = pos[3 * n + 2] - pos[3 * j + 2];
        float d = sqrtf(dx * dx + dy * dy + dz * dz);
        g_invd[i] = (d == 0.0f) ? 2.0f : 1.0f / d;
    } else if (b < 8256) {
        int i = (b - 8192) * 256 + tid;          // K=128, N=128
        int k = i >> 7, n = i & 127;
        g_wt0h[n * 128 + k] = __float2half_rn(W0[i]);
    } else if (b < 8768) {
        int i = (b - 8256) * 256 + tid;          // K=1024, N=128
        int k = i >> 7, n = i & 127;
        g_wt1h[n * 1024 + k] = __float2half_rn(W1[i]);
    } else {
        int i = (b - 8768) * 256 + tid;          // Wcat2
        int c = i >> 7, f = i & 127;
        int k = c >> 4, j = c & 15;
        g_wt2c[i] = __float2half_rn(W2[(k * 128 + f) * 16 + j]);
    }
}

// ============ layer 1 + fused Z GEMM (TM=128, 32x64 warp tiles) ============
struct P1 {
    static constexpr int KC = 64, KTOT = 1024, NCH = 16;
    static constexpr int ABUF = 128 * 128, BBUF = 128 * 128;
    static constexpr int STRIDE = ABUF + BBUF;
    static constexpr int OFF_SN = 0, OFF_SH = 4096, BASE = 8192;
    static __device__ __forceinline__ int offA(int b) { return BASE + b * STRIDE; }
    static __device__ __forceinline__ int offB(int b) { return BASE + b * STRIDE + ABUF; }
    static constexpr int SMEM_BYTES = BASE + 2 * STRIDE;   // 73728
};

__global__ void __launch_bounds__(256, 2)
layer1_kernel(const __half* __restrict__ hin, const int* __restrict__ nbr,
              const __half* __restrict__ wh, const __half* __restrict__ wcat,
              const float* __restrict__ bg, __half* __restrict__ Z) {
    using C = P1;
    extern __shared__ char smem[];
    const uint32_t sbase = smem_u32(smem);
    const int tid = threadIdx.x, wid = tid >> 5, lane = tid & 31;
    const int n0 = blockIdx.x * 128;

    int* sN = (int*)(smem + C::OFF_SN);
    uint32_t* sH = (uint32_t*)(smem + C::OFF_SH);   // half2 broadcast of invd
    for (int idx = tid; idx < 128 * KNBR; idx += 256) {
        sN[idx] = nbr[n0 * KNBR + idx];
        __half2 s2 = __float2half2_rn(g_invd[(size_t)n0 * KNBR + idx]);
        sH[idx] = *reinterpret_cast<uint32_t*>(&s2);
    }
    float acc[16][4];
#pragma unroll
    for (int t = 0; t < 16; t++) {
        acc[t][0] = 0.f; acc[t][1] = 0.f; acc[t][2] = 0.f; acc[t][3] = 0.f;
    }
    __syncthreads();

    auto stageB = [&](int ch, int buf) {
#pragma unroll 2
        for (int idx = tid; idx < 128 * 8; idx += 256) {
            int row = idx >> 3, c = idx & 7;
            cp_async16(sbase + C::offB(buf) + swz128((uint32_t)(row * 128 + c * 16)),
                       wh + (size_t)row * C::KTOT + ch * C::KC + c * 8);
        }
        asm volatile("cp.async.commit_group;");
    };
    auto convA = [&](int buf, int idx, uint4 v, uint32_t s) {
        int row = idx >> 3, q8 = idx & 7;
        __half2 s2 = *reinterpret_cast<__half2*>(&s);
        __half2* hv = reinterpret_cast<__half2*>(&v);
#pragma unroll
        for (int p = 0; p < 4; p++) hv[p] = __hmul2(hv[p], s2);
        *reinterpret_cast<uint4*>(smem + C::offA(buf) +
                                  swz128((uint32_t)(row * 128 + q8 * 16))) = v;
    };

    stageB(0, 0);
#pragma unroll
    for (int t = 0; t < 4; t++) {
        int idx = tid + t * 256;
        int row = idx >> 3, q8 = idx & 7;
        int k = (q8 * 8) >> 7, f = (q8 * 8) & 127;
        uint4 v = *reinterpret_cast<const uint4*>(
            hin + (size_t)sN[row * KNBR + k] * 128 + f);
        convA(0, idx, v, sH[row * KNBR + k]);
    }
    asm volatile("cp.async.wait_group 0;");
    __syncthreads();

    const int mat = lane >> 3, r = lane & 7;
    const int wy = wid >> 1, wx = wid & 1;

    uint4 av[4];
    for (int ch = 0; ch < C::NCH; ch++) {
        const int cur = ch & 1;
        const bool more = (ch + 1 < C::NCH);
        if (more) {
            stageB(ch + 1, cur ^ 1);
#pragma unroll
            for (int t = 0; t < 4; t++) {
                int idx = tid + t * 256;
                int row = idx >> 3, q8 = idx & 7;
                int j = (ch + 1) * C::KC + q8 * 8;
                av[t] = *reinterpret_cast<const uint4*>(
                    hin + (size_t)sN[row * KNBR + (j >> 7)] * 128 + (j & 127));
            }
        }
#pragma unroll
        for (int ks = 0; ks < 4; ks++) {
            uint32_t ah[2][4];
#pragma unroll
            for (int am = 0; am < 2; am++) {
                int arow = wy * 32 + am * 16 + ((mat & 1) << 3) + r;
                int acol = (ks << 4) + ((mat >> 1) << 3);
                ldsm4(ah[am], sbase + C::offA(cur) +
                      swz128((uint32_t)(arow * 128 + acol * 2)));
            }
#pragma unroll
            for (int bn = 0; bn < 4; bn++) {
                int brow = wx * 64 + bn * 16 + ((mat >> 1) << 3) + r;
                int bcol = (ks << 4) + ((mat & 1) << 3);
                uint32_t bh[4];
                ldsm4(bh, sbase + C::offB(cur) +
                      swz128((uint32_t)(brow * 128 + bcol * 2)));
#pragma unroll
                for (int am = 0; am < 2; am++) {
                    mma16816(acc[am * 8 + bn * 2], ah[am], bh[0], bh[1]);
                    mma16816(acc[am * 8 + bn * 2 + 1], ah[am], bh[2], bh[3]);
                }
            }
        }
        if (more) {
#pragma unroll
            for (int t = 0; t < 4; t++) {
                int idx = tid + t * 256;
                int row = idx >> 3;
                int j = (ch + 1) * C::KC + (idx & 7) * 8;
                convA(cur ^ 1, idx, av[t], sH[row * KNBR + (j >> 7)]);
            }
            asm volatile("cp.async.wait_group 0;");
        }
        __syncthreads();
    }

    // ---- fused epilogue: h2 = act(acc + b1) -> smem; Z = h2 @ Wcat ----
#pragma unroll 2
    for (int idx = tid; idx < 2048; idx += 256) {
        int ch2 = idx >> 10, rem = idx & 1023;
        int row = rem >> 3, c = rem & 7;
        cp_async16(sbase + C::offB(ch2) + swz128((uint32_t)(row * 128 + c * 16)),
                   wcat + (size_t)row * 128 + ch2 * 64 + c * 8);
    }
    asm volatile("cp.async.commit_group;");

    const int g = lane >> 2, tig = lane & 3;
#pragma unroll
    for (int am = 0; am < 2; am++) {
        int row0 = wy * 32 + am * 16 + g;
#pragma unroll
        for (int bn = 0; bn < 4; bn++) {
#pragma unroll
            for (int half = 0; half < 2; half++) {
                int col = wx * 64 + bn * 16 + half * 8 + tig * 2;
                const float* d = acc[am * 8 + bn * 2 + half];
                float b0 = bg[col], b1 = bg[col + 1];
                float v00 = d[0] + b0, v01 = d[1] + b1;
                float v10 = d[2] + b0, v11 = d[3] + b1;
                v00 = (v00 >= 0.f) ? v00 : 0.01f * v00;
                v01 = (v01 >= 0.f) ? v01 : 0.01f * v01;
                v10 = (v10 >= 0.f) ? v10 : 0.01f * v10;
                v11 = (v11 >= 0.f) ? v11 : 0.01f * v11;
                int ch2 = col >> 6, cc = col & 63;
                *reinterpret_cast<uint32_t*>(
                    smem + C::offA(ch2) + swz128((uint32_t)(row0 * 128 + cc * 2))) =
                    pack_h2(v00, v01);
                *reinterpret_cast<uint32_t*>(
                    smem + C::offA(ch2) +
                    swz128((uint32_t)((row0 + 8) * 128 + cc * 2))) = pack_h2(v10, v11);
            }
        }
    }
    asm volatile("cp.async.wait_group 0;");
    __syncthreads();

#pragma unroll
    for (int t = 0; t < 16; t++) {
        acc[t][0] = 0.f; acc[t][1] = 0.f; acc[t][2] = 0.f; acc[t][3] = 0.f;
    }
#pragma unroll
    for (int ch2 = 0; ch2 < 2; ch2++) {
#pragma unroll
        for (int ks = 0; ks < 4; ks++) {
            uint32_t ah[2][4];
#pragma unroll
            for (int am = 0; am < 2; am++) {
                int arow = wy * 32 + am * 16 + ((mat & 1) << 3) + r;
                int acol = (ks << 4) + ((mat >> 1) << 3);
                ldsm4(ah[am], sbase + C::offA(ch2) +
                      swz128((uint32_t)(arow * 128 + acol * 2)));
            }
#pragma unroll
            for (int bn = 0; bn < 4; bn++) {
                int brow = wx * 64 + bn * 16 + ((mat >> 1) << 3) + r;
                int bcol = (ks << 4) + ((mat & 1) << 3);
                uint32_t bh[4];
                ldsm4(bh, sbase + C::offB(ch2) +
                      swz128((uint32_t)(brow * 128 + bcol * 2)));
#pragma unroll
                for (int am = 0; am < 2; am++) {
                    mma16816(acc[am * 8 + bn * 2], ah[am], bh[0], bh[1]);
                    mma16816(acc[am * 8 + bn * 2 + 1], ah[am], bh[2], bh[3]);
                }
            }
        }
    }

    // Z stores with L2 evict_last (keep resident for combine2)
    uint64_t pol;
    asm("createpolicy.fractional.L2::evict_last.b64 %0, 1.0;" : "=l"(pol));
#pragma unroll
    for (int am = 0; am < 2; am++) {
        int row0 = n0 + wy * 32 + am * 16 + g;
#pragma unroll
        for (int bn = 0; bn < 4; bn++) {
#pragma unroll
            for (int half = 0; half < 2; half++) {
                int col = wx * 64 + bn * 16 + half * 8 + tig * 2;
                const float* d = acc[am * 8 + bn * 2 + half];
                stg_b32_evict_last(Z + (size_t)row0 * 128 + col,
                                   pack_h2(d[0], d[1]), pol);
                stg_b32_evict_last(Z + (size_t)(row0 + 8) * 128 + col,
                                   pack_h2(d[2], d[3]), pol);
            }
        }
    }
}

// ============ layer 0: pipelined single-pass fp16 (fp32 input h[N,16]) =====
struct P0 {
    static constexpr int KC = 64, NCH = 2;
    static constexpr int ABUF = 128 * 128, BBUF = 128 * 128;
    static constexpr int STRIDE = ABUF + BBUF;
    static constexpr int OFF_SN = 0, OFF_SD = 4096, BASE = 8192;
    static __device__ __forceinline__ int offA(int b) { return BASE + b * STRIDE; }
    static __device__ __forceinline__ int offB(int b) { return BASE + b * STRIDE + ABUF; }
    static constexpr int SMEM_BYTES = BASE + 2 * STRIDE;   // 73728
};

__global__ void __launch_bounds__(256, 2)
layer0_kernel(const float* __restrict__ hin, const int* __restrict__ nbr,
              const __half* __restrict__ wh, const float* __restrict__ bg,
              __half* __restrict__ out) {
    using C = P0;
    constexpr int FIN = 16, FOUT = 128, KTOT = 128;
    extern __shared__ char smem[];
    const uint32_t sbase = smem_u32(smem);
    const int tid = threadIdx.x, wid = tid >> 5, lane = tid & 31;
    const int n0 = blockIdx.x * 128;

    int* sN = (int*)(smem + C::OFF_SN);
    float* sD = (float*)(smem + C::OFF_SD);
    for (int idx = tid; idx < 128 * KNBR; idx += 256) {
        sN[idx] = nbr[n0 * KNBR + idx];
        sD[idx] = g_invd[(size_t)n0 * KNBR + idx];
    }
    float acc[FOUT / 8][4];
#pragma unroll
    for (int t = 0; t < FOUT / 8; t++) {
        acc[t][0] = 0.f; acc[t][1] = 0.f; acc[t][2] = 0.f; acc[t][3] = 0.f;
    }
    __syncthreads();

    auto stageB = [&](int ch, int buf) {
        for (int idx = tid; idx < FOUT * 8; idx += 256) {
            int row = idx >> 3, c = idx & 7;
            cp_async16(sbase + C::offB(buf) + swz128((uint32_t)(row * 128 + c * 16)),
                       wh + (size_t)row * KTOT + ch * C::KC + c * 8);
        }
        asm volatile("cp.async.commit_group;");
    };
    auto convA = [&](int buf, int idx, float4 v, float s) {
        int row = idx >> 4, q = idx & 15;
        uint32_t ph0 = pack_h2(v.x * s, v.y * s);
        uint32_t ph1 = pack_h2(v.z * s, v.w * s);
        *reinterpret_cast<uint2*>(smem + C::offA(buf) +
                                  swz128((uint32_t)(row * 128 + q * 8))) =
            make_uint2(ph0, ph1);
    };

    // prologue: chunk 0
    stageB(0, 0);
#pragma unroll
    for (int t = 0; t < 8; t++) {
        int idx = tid + t * 256;
        int row = idx >> 4, q = idx & 15;
        int j = q * 4;
        int k = j / FIN, f = j % FIN;
        float4 v = *reinterpret_cast<const float4*>(
            hin + (size_t)sN[row * KNBR + k] * FIN + f);
        convA(0, idx, v, sD[row * KNBR + k]);
    }
    asm volatile("cp.async.wait_group 0;");
    __syncthreads();

    const int mat = lane >> 3, r = lane & 7;
    const int mrow = wid * 16;

    float4 av[8];
    for (int ch = 0; ch < C::NCH; ch++) {
        const int cur = ch & 1;
        const bool more = (ch + 1 < C::NCH);
        if (more) {
            stageB(ch + 1, cur ^ 1);
#pragma unroll
            for (int t = 0; t < 8; t++) {
                int idx = tid + t * 256;
                int row = idx >> 4, q = idx & 15;
                int j = (ch + 1) * C::KC + q * 4;
                int k = j / FIN, f = j % FIN;
                av[t] = *reinterpret_cast<const float4*>(
                    hin + (size_t)sN[row * KNBR + k] * FIN + f);
            }
        }
#pragma unroll
        for (int ks = 0; ks < C::KC / 16; ks++) {
            int arow = mrow + ((mat & 1) << 3) + r;
            int acol = (ks << 4) + ((mat >> 1) << 3);
            uint32_t ah[4];
            ldsm4(ah, sbase + C::offA(cur) +
                  swz128((uint32_t)(arow * 128 + acol * 2)));
#pragma unroll
            for (int nt2 = 0; nt2 < FOUT / 16; nt2++) {
                int brow = nt2 * 16 + ((mat >> 1) << 3) + r;
                int bcol = (ks << 4) + ((mat & 1) << 3);
                uint32_t bh[4];
                ldsm4(bh, sbase + C::offB(cur) +
                      swz128((uint32_t)(brow * 128 + bcol * 2)));
                mma16816(acc[nt2 * 2], ah, bh[0], bh[1]);
                mma16816(acc[nt2 * 2 + 1], ah, bh[2], bh[3]);
            }
        }
        if (more) {
#pragma unroll
            for (int t = 0; t < 8; t++) {
                int idx = tid + t * 256;
                int row = idx >> 4, q = idx & 15;
                int j = (ch + 1) * C::KC + q * 4;
                int k = j / FIN;
                convA(cur ^ 1, idx, av[t], sD[row * KNBR + k]);
            }
            asm volatile("cp.async.wait_group 0;");
            __syncthreads();
        }
    }

    const int g = lane >> 2, tig = lane & 3;
    const int row0 = n0 + mrow + g;
#pragma unroll
    for (int nt = 0; nt < FOUT / 8; nt++) {
        int col = nt * 8 + tig * 2;
        float b0 = bg[col], b1 = bg[col + 1];
        *reinterpret_cast<uint32_t*>(out + (size_t)row0 * FOUT + col) =
            pack_h2(acc[nt][0] + b0, acc[nt][1] + b1);
        *reinterpret_cast<uint32_t*>(out + (size_t)(row0 + 8) * FOUT + col) =
            pack_h2(acc[nt][2] + b0, acc[nt][3] + b1);
    }
}

// ============ combine: out[n] = b2 + sum_k invd[n,k] * Z16[nbr[n,k], k*16:] =
__global__ void __launch_bounds__(256)
combine2_kernel(const int* __restrict__ nbr, const __half* __restrict__ Z,
                const float* __restrict__ b2, float* __restrict__ out) {
    int n = blockIdx.x * 256 + threadIdx.x;
    const int4* nb = reinterpret_cast<const int4*>(nbr + (size_t)n * 8);
    int4 nb0 = nb[0], nb1 = nb[1];
    const float4* iv = reinterpret_cast<const float4*>(g_invd + (size_t)n * 8);
    float4 s0 = iv[0], s1 = iv[1];
    int idx[8] = {nb0.x, nb0.y, nb0.z, nb0.w, nb1.x, nb1.y, nb1.z, nb1.w};
    float sc[8] = {s0.x, s0.y, s0.z, s0.w, s1.x, s1.y, s1.z, s1.w};
    float acc[16];
#pragma unroll
    for (int q = 0; q < 4; q++) {
        float4 b = reinterpret_cast<const float4*>(b2)[q];
        acc[q * 4 + 0] = b.x; acc[q * 4 + 1] = b.y;
        acc[q * 4 + 2] = b.z; acc[q * 4 + 3] = b.w;
    }
#pragma unroll
    for (int k = 0; k < 8; k++) {
        const uint4* zp = reinterpret_cast<const uint4*>(
            Z + (size_t)idx[k] * 128 + k * 16);
        uint4 za = zp[0], zb = zp[1];
        const uint32_t zw[8] = {za.x, za.y, za.z, za.w, zb.x, zb.y, zb.z, zb.w};
        float s = sc[k];
#pragma unroll
        for (int q = 0; q < 8; q++) {
            float2 z = __half22float2(*reinterpret_cast<const __half2*>(&zw[q]));
            acc[q * 2 + 0] += s * z.x;
            acc[q * 2 + 1] += s * z.y;
        }
    }
    float4* op = reinterpret_cast<float4*>(out + (size_t)n * 16);
#pragma unroll
    for (int q = 0; q < 4; q++)
        op[q] = make_float4(acc[q * 4], acc[q * 4 + 1], acc[q * 4 + 2], acc[q * 4 + 3]);
}

// ---------------- host launch ----------------
extern "C" void kernel_launch(void* const* d_in, const int* in_sizes, int n_in,
                              void* d_out, int out_size) {
    const float* h   = (const float*)d_in[0];
    const float* pos = (const float*)d_in[1];
    const int*   nbr = (const int*)d_in[2];
    const float* W0  = (const float*)d_in[3];
    const float* b0  = (const float*)d_in[4];
    const float* W1  = (const float*)d_in[5];
    const float* b1  = (const float*)d_in[6];
    const float* W2  = (const float*)d_in[7];
    const float* b2  = (const float*)d_in[8];
    float* out = (float*)d_out;

    __half *h1, *z, *wt0, *wt1, *wt2c;
    cudaGetSymbolAddress((void**)&h1, g_h1);
    cudaGetSymbolAddress((void**)&z, g_z);
    cudaGetSymbolAddress((void**)&wt0, g_wt0h);
    cudaGetSymbolAddress((void**)&wt1, g_wt1h);
    cudaGetSymbolAddress((void**)&wt2c, g_wt2c);

    constexpr int SM0 = P0::SMEM_BYTES;         // 73728
    constexpr int SM1 = P1::SMEM_BYTES;         // 73728

    cudaFuncSetAttribute((const void*)layer0_kernel,
                         cudaFuncAttributeMaxDynamicSharedMemorySize, SM0);
    cudaFuncSetAttribute((const void*)layer1_kernel,
                         cudaFuncAttributeMaxDynamicSharedMemorySize, SM1);

    prep_kernel<<<8832, 256>>>(pos, nbr, W0, W1, W2);
    layer0_kernel<<<NNODES / 128, 256, SM0>>>(h, nbr, wt0, b0, h1);
    layer1_kernel<<<NNODES / 128, 256, SM1>>>(h1, nbr, wt1, wt2c, b1, z);
    combine2_kernel<<<NNODES / 256, 256>>>(nbr, z, b2, out);
}

// round 15
// speedup vs baseline: 1.0169x; 1.0169x over previous
#include <cuda_runtime.h>
#include <cuda_fp16.h>
#include <cstdint>
#include <math.h>

#define NNODES 262144
#define KNBR 8

// ---------------- global scratch (allocation-free) ----------------
__device__ __half g_h1[(size_t)NNODES * 128];   // fp16 intermediate
__device__ __half g_z[(size_t)NNODES * 128];    // Z = h2 @ Wcat2 (fp16)
__device__ float  g_invd[(size_t)NNODES * KNBR];
__device__ __half g_wt0h[128 * 128];            // W0^T [N,K] fp16
__device__ __half g_wt1h[128 * 1024];           // W1^T [N,K] fp16
__device__ __half g_wt2c[128 * 128];            // Wcat2^T [c=k*16+j][f] fp16

// ---------------- helpers ----------------
__device__ __forceinline__ uint32_t smem_u32(const void* p) {
    uint32_t a;
    asm("{ .reg .u64 t; cvta.to.shared.u64 t, %1; cvt.u32.u64 %0, t; }"
        : "=r"(a) : "l"(p));
    return a;
}
__device__ __forceinline__ uint32_t swz128(uint32_t off) {
    return off ^ ((off >> 3) & 0x70);
}
__device__ __forceinline__ void ldsm4(uint32_t* r, uint32_t addr) {
    asm volatile("ldmatrix.sync.aligned.m8n8.x4.shared.b16 {%0,%1,%2,%3}, [%4];"
                 : "=r"(r[0]), "=r"(r[1]), "=r"(r[2]), "=r"(r[3]) : "r"(addr));
}
__device__ __forceinline__ void mma16816(float* d, const uint32_t* a,
                                         uint32_t b0, uint32_t b1) {
    asm volatile(
        "mma.sync.aligned.m16n8k16.row.col.f32.f16.f16.f32 "
        "{%0,%1,%2,%3}, {%4,%5,%6,%7}, {%8,%9}, {%0,%1,%2,%3};"
        : "+f"(d[0]), "+f"(d[1]), "+f"(d[2]), "+f"(d[3])
        : "r"(a[0]), "r"(a[1]), "r"(a[2]), "r"(a[3]), "r"(b0), "r"(b1));
}
__device__ __forceinline__ uint32_t pack_h2(float a, float b) {
    uint32_t d;
    asm("cvt.rn.f16x2.f32 %0, %1, %2;" : "=r"(d) : "f"(b), "f"(a));
    return d;
}
__device__ __forceinline__ void cp_async16(uint32_t dst, const void* src) {
    asm volatile("cp.async.cg.shared.global [%0], [%1], 16;"
                 :: "r"(dst), "l"(src));
}

// ---------------- merged prep kernel ----------------
// blocks [0,8192): invdist; [8192,8256): W0^T; [8256,8768): W1^T; [8768,8832): Wcat2
__global__ void __launch_bounds__(256)
prep_kernel(const float* __restrict__ pos, const int* __restrict__ nbr,
            const float* __restrict__ W0, const float* __restrict__ W1,
            const float* __restrict__ W2) {
    int b = blockIdx.x, tid = threadIdx.x;
    if (b < 8192) {
        int i = b * 256 + tid;
        int n = i >> 3;
        int j = nbr[i];
        float dx = pos[3 * n + 0] - pos[3 * j + 0];
        float dy = pos[3 * n + 1] - pos[3 * j + 1];
        float dz = pos[3 * n + 2] - pos[3 * j + 2];
        float d = sqrtf(dx * dx + dy * dy + dz * dz);
        g_invd[i] = (d == 0.0f) ? 2.0f : 1.0f / d;
    } else if (b < 8256) {
        int i = (b - 8192) * 256 + tid;          // K=128, N=128
        int k = i >> 7, n = i & 127;
        g_wt0h[n * 128 + k] = __float2half_rn(W0[i]);
    } else if (b < 8768) {
        int i = (b - 8256) * 256 + tid;          // K=1024, N=128
        int k = i >> 7, n = i & 127;
        g_wt1h[n * 1024 + k] = __float2half_rn(W1[i]);
    } else {
        int i = (b - 8768) * 256 + tid;          // Wcat2
        int c = i >> 7, f = i & 127;
        int k = c >> 4, j = c & 15;
        g_wt2c[i] = __float2half_rn(W2[(k * 128 + f) * 16 + j]);
    }
}

// ============ layer 1 + fused Z GEMM (TM=128, cp.async gather staging) =====
struct P1 {
    static constexpr int KC = 64, KTOT = 1024, NCH = 16;
    static constexpr int ABUF = 128 * 128, BBUF = 128 * 128;   // 16KB each
    static constexpr int SBUF = 128 * 128;                     // raw gather 16KB
    static constexpr int STRIDE = ABUF + BBUF;
    static constexpr int OFF_SN = 0, OFF_SH = 4096, BASE = 8192;
    static __device__ __forceinline__ int offA(int b) { return BASE + b * STRIDE; }
    static __device__ __forceinline__ int offB(int b) { return BASE + b * STRIDE + ABUF; }
    static __device__ __forceinline__ int offS(int b) { return BASE + 2 * STRIDE + b * SBUF; }
    static constexpr int SMEM_BYTES = BASE + 2 * STRIDE + 2 * SBUF;   // 106496
};

__global__ void __launch_bounds__(256, 2)
layer1_kernel(const __half* __restrict__ hin, const int* __restrict__ nbr,
              const __half* __restrict__ wh, const __half* __restrict__ wcat,
              const float* __restrict__ bg, __half* __restrict__ Z) {
    using C = P1;
    extern __shared__ char smem[];
    const uint32_t sbase = smem_u32(smem);
    const int tid = threadIdx.x, wid = tid >> 5, lane = tid & 31;
    const int n0 = blockIdx.x * 128;

    int* sN = (int*)(smem + C::OFF_SN);
    uint32_t* sH = (uint32_t*)(smem + C::OFF_SH);   // half2 broadcast of invd
    for (int idx = tid; idx < 128 * KNBR; idx += 256) {
        sN[idx] = nbr[n0 * KNBR + idx];
        __half2 s2 = __float2half2_rn(g_invd[(size_t)n0 * KNBR + idx]);
        sH[idx] = *reinterpret_cast<uint32_t*>(&s2);
    }
    float acc[16][4];
#pragma unroll
    for (int t = 0; t < 16; t++) {
        acc[t][0] = 0.f; acc[t][1] = 0.f; acc[t][2] = 0.f; acc[t][3] = 0.f;
    }
    __syncthreads();

    // stage W chunk + raw gathered h1 chunk via cp.async (one commit group)
    auto stageB = [&](int ch, int buf) {
#pragma unroll 2
        for (int idx = tid; idx < 128 * 8; idx += 256) {
            int row = idx >> 3, c = idx & 7;
            cp_async16(sbase + C::offB(buf) + swz128((uint32_t)(row * 128 + c * 16)),
                       wh + (size_t)row * C::KTOT + ch * C::KC + c * 8);
        }
    };
    auto stageG = [&](int ch, int buf) {
        int k = ch >> 1, fbase = (ch & 1) * 64;
#pragma unroll
        for (int t = 0; t < 4; t++) {
            int idx = tid + t * 256;
            int row = idx >> 3, q8 = idx & 7;
            cp_async16(sbase + C::offS(buf) + idx * 16,
                       hin + (size_t)sN[row * KNBR + k] * 128 + fbase + q8 * 8);
        }
    };
    // conv: staging -> scale -> swizzled A
    auto convA = [&](int buf, int ch) {
        int k = ch >> 1;
#pragma unroll
        for (int t = 0; t < 4; t++) {
            int idx = tid + t * 256;
            int row = idx >> 3, q8 = idx & 7;
            uint4 v = *reinterpret_cast<uint4*>(smem + C::offS(buf) + idx * 16);
            uint32_t s = sH[row * KNBR + k];
            __half2 s2 = *reinterpret_cast<__half2*>(&s);
            __half2* hv = reinterpret_cast<__half2*>(&v);
#pragma unroll
            for (int p = 0; p < 4; p++) hv[p] = __hmul2(hv[p], s2);
            *reinterpret_cast<uint4*>(smem + C::offA(buf) +
                                      swz128((uint32_t)(row * 128 + q8 * 16))) = v;
        }
    };

    // prologue
    stageB(0, 0);
    stageG(0, 0);
    asm volatile("cp.async.commit_group;");
    asm volatile("cp.async.wait_group 0;");
    __syncthreads();
    convA(0, 0);
    __syncthreads();

    const int mat = lane >> 3, r = lane & 7;
    const int wy = wid >> 1, wx = wid & 1;

    for (int ch = 0; ch < C::NCH; ch++) {
        const int cur = ch & 1;
        const bool more = (ch + 1 < C::NCH);
        if (more) {
            stageB(ch + 1, cur ^ 1);
            stageG(ch + 1, cur ^ 1);
            asm volatile("cp.async.commit_group;");
        }
#pragma unroll
        for (int ks = 0; ks < 4; ks++) {
            uint32_t ah[2][4];
#pragma unroll
            for (int am = 0; am < 2; am++) {
                int arow = wy * 32 + am * 16 + ((mat & 1) << 3) + r;
                int acol = (ks << 4) + ((mat >> 1) << 3);
                ldsm4(ah[am], sbase + C::offA(cur) +
                      swz128((uint32_t)(arow * 128 + acol * 2)));
            }
#pragma unroll
            for (int bn = 0; bn < 4; bn++) {
                int brow = wx * 64 + bn * 16 + ((mat >> 1) << 3) + r;
                int bcol = (ks << 4) + ((mat & 1) << 3);
                uint32_t bh[4];
                ldsm4(bh, sbase + C::offB(cur) +
                      swz128((uint32_t)(brow * 128 + bcol * 2)));
#pragma unroll
                for (int am = 0; am < 2; am++) {
                    mma16816(acc[am * 8 + bn * 2], ah[am], bh[0], bh[1]);
                    mma16816(acc[am * 8 + bn * 2 + 1], ah[am], bh[2], bh[3]);
                }
            }
        }
        if (more) {
            asm volatile("cp.async.wait_group 0;");
            convA(cur ^ 1, ch + 1);
        }
        __syncthreads();
    }

    // ---- fused epilogue: h2 = act(acc + b1) -> smem; Z = h2 @ Wcat ----
#pragma unroll 2
    for (int idx = tid; idx < 2048; idx += 256) {
        int ch2 = idx >> 10, rem = idx & 1023;
        int row = rem >> 3, c = rem & 7;
        cp_async16(sbase + C::offB(ch2) + swz128((uint32_t)(row * 128 + c * 16)),
                   wcat + (size_t)row * 128 + ch2 * 64 + c * 8);
    }
    asm volatile("cp.async.commit_group;");

    const int g = lane >> 2, tig = lane & 3;
#pragma unroll
    for (int am = 0; am < 2; am++) {
        int row0 = wy * 32 + am * 16 + g;
#pragma unroll
        for (int bn = 0; bn < 4; bn++) {
#pragma unroll
            for (int half = 0; half < 2; half++) {
                int col = wx * 64 + bn * 16 + half * 8 + tig * 2;
                const float* d = acc[am * 8 + bn * 2 + half];
                float b0 = bg[col], b1 = bg[col + 1];
                float v00 = d[0] + b0, v01 = d[1] + b1;
                float v10 = d[2] + b0, v11 = d[3] + b1;
                v00 = (v00 >= 0.f) ? v00 : 0.01f * v00;
                v01 = (v01 >= 0.f) ? v01 : 0.01f * v01;
                v10 = (v10 >= 0.f) ? v10 : 0.01f * v10;
                v11 = (v11 >= 0.f) ? v11 : 0.01f * v11;
                int ch2 = col >> 6, cc = col & 63;
                *reinterpret_cast<uint32_t*>(
                    smem + C::offA(ch2) + swz128((uint32_t)(row0 * 128 + cc * 2))) =
                    pack_h2(v00, v01);
                *reinterpret_cast<uint32_t*>(
                    smem + C::offA(ch2) +
                    swz128((uint32_t)((row0 + 8) * 128 + cc * 2))) = pack_h2(v10, v11);
            }
        }
    }
    asm volatile("cp.async.wait_group 0;");
    __syncthreads();

#pragma unroll
    for (int t = 0; t < 16; t++) {
        acc[t][0] = 0.f; acc[t][1] = 0.f; acc[t][2] = 0.f; acc[t][3] = 0.f;
    }
#pragma unroll
    for (int ch2 = 0; ch2 < 2; ch2++) {
#pragma unroll
        for (int ks = 0; ks < 4; ks++) {
            uint32_t ah[2][4];
#pragma unroll
            for (int am = 0; am < 2; am++) {
                int arow = wy * 32 + am * 16 + ((mat & 1) << 3) + r;
                int acol = (ks << 4) + ((mat >> 1) << 3);
                ldsm4(ah[am], sbase + C::offA(ch2) +
                      swz128((uint32_t)(arow * 128 + acol * 2)));
            }
#pragma unroll
            for (int bn = 0; bn < 4; bn++) {
                int brow = wx * 64 + bn * 16 + ((mat >> 1) << 3) + r;
                int bcol = (ks << 4) + ((mat & 1) << 3);
                uint32_t bh[4];
                ldsm4(bh, sbase + C::offB(ch2) +
                      swz128((uint32_t)(brow * 128 + bcol * 2)));
#pragma unroll
                for (int am = 0; am < 2; am++) {
                    mma16816(acc[am * 8 + bn * 2], ah[am], bh[0], bh[1]);
                    mma16816(acc[am * 8 + bn * 2 + 1], ah[am], bh[2], bh[3]);
                }
            }
        }
    }

#pragma unroll
    for (int am = 0; am < 2; am++) {
        int row0 = n0 + wy * 32 + am * 16 + g;
#pragma unroll
        for (int bn = 0; bn < 4; bn++) {
#pragma unroll
            for (int half = 0; half < 2; half++) {
                int col = wx * 64 + bn * 16 + half * 8 + tig * 2;
                const float* d = acc[am * 8 + bn * 2 + half];
                *reinterpret_cast<uint32_t*>(Z + (size_t)row0 * 128 + col) =
                    pack_h2(d[0], d[1]);
                *reinterpret_cast<uint32_t*>(Z + (size_t)(row0 + 8) * 128 + col) =
                    pack_h2(d[2], d[3]);
            }
        }
    }
}

// ============ layer 0: pipelined single-pass fp16 (fp32 input h[N,16]) =====
struct P0 {
    static constexpr int KC = 64, NCH = 2;
    static constexpr int ABUF = 128 * 128, BBUF = 128 * 128;
    static constexpr int STRIDE = ABUF + BBUF;
    static constexpr int OFF_SN = 0, OFF_SD = 4096, BASE = 8192;
    static __device__ __forceinline__ int offA(int b) { return BASE + b * STRIDE; }
    static __device__ __forceinline__ int offB(int b) { return BASE + b * STRIDE + ABUF; }
    static constexpr int SMEM_BYTES = BASE + 2 * STRIDE;   // 73728
};

__global__ void __launch_bounds__(256, 2)
layer0_kernel(const float* __restrict__ hin, const int* __restrict__ nbr,
              const __half* __restrict__ wh, const float* __restrict__ bg,
              __half* __restrict__ out) {
    using C = P0;
    constexpr int FIN = 16, FOUT = 128, KTOT = 128;
    extern __shared__ char smem[];
    const uint32_t sbase = smem_u32(smem);
    const int tid = threadIdx.x, wid = tid >> 5, lane = tid & 31;
    const int n0 = blockIdx.x * 128;

    int* sN = (int*)(smem + C::OFF_SN);
    float* sD = (float*)(smem + C::OFF_SD);
    for (int idx = tid; idx < 128 * KNBR; idx += 256) {
        sN[idx] = nbr[n0 * KNBR + idx];
        sD[idx] = g_invd[(size_t)n0 * KNBR + idx];
    }
    float acc[FOUT / 8][4];
#pragma unroll
    for (int t = 0; t < FOUT / 8; t++) {
        acc[t][0] = 0.f; acc[t][1] = 0.f; acc[t][2] = 0.f; acc[t][3] = 0.f;
    }
    __syncthreads();

    auto stageB = [&](int ch, int buf) {
        for (int idx = tid; idx < FOUT * 8; idx += 256) {
            int row = idx >> 3, c = idx & 7;
            cp_async16(sbase + C::offB(buf) + swz128((uint32_t)(row * 128 + c * 16)),
                       wh + (size_t)row * KTOT + ch * C::KC + c * 8);
        }
        asm volatile("cp.async.commit_group;");
    };
    auto convA = [&](int buf, int idx, float4 v, float s) {
        int row = idx >> 4, q = idx & 15;
        uint32_t ph0 = pack_h2(v.x * s, v.y * s);
        uint32_t ph1 = pack_h2(v.z * s, v.w * s);
        *reinterpret_cast<uint2*>(smem + C::offA(buf) +
                                  swz128((uint32_t)(row * 128 + q * 8))) =
            make_uint2(ph0, ph1);
    };

    // prologue: chunk 0
    stageB(0, 0);
#pragma unroll
    for (int t = 0; t < 8; t++) {
        int idx = tid + t * 256;
        int row = idx >> 4, q = idx & 15;
        int j = q * 4;
        int k = j / FIN, f = j % FIN;
        float4 v = *reinterpret_cast<const float4*>(
            hin + (size_t)sN[row * KNBR + k] * FIN + f);
        convA(0, idx, v, sD[row * KNBR + k]);
    }
    asm volatile("cp.async.wait_group 0;");
    __syncthreads();

    const int mat = lane >> 3, r = lane & 7;
    const int mrow = wid * 16;

    float4 av[8];
    for (int ch = 0; ch < C::NCH; ch++) {
        const int cur = ch & 1;
        const bool more = (ch + 1 < C::NCH);
        if (more) {
            stageB(ch + 1, cur ^ 1);
#pragma unroll
            for (int t = 0; t < 8; t++) {
                int idx = tid + t * 256;
                int row = idx >> 4, q = idx & 15;
                int j = (ch + 1) * C::KC + q * 4;
                int k = j / FIN, f = j % FIN;
                av[t] = *reinterpret_cast<const float4*>(
                    hin + (size_t)sN[row * KNBR + k] * FIN + f);
            }
        }
#pragma unroll
        for (int ks = 0; ks < C::KC / 16; ks++) {
            int arow = mrow + ((mat & 1) << 3) + r;
            int acol = (ks << 4) + ((mat >> 1) << 3);
            uint32_t ah[4];
            ldsm4(ah, sbase + C::offA(cur) +
                  swz128((uint32_t)(arow * 128 + acol * 2)));
#pragma unroll
            for (int nt2 = 0; nt2 < FOUT / 16; nt2++) {
                int brow = nt2 * 16 + ((mat >> 1) << 3) + r;
                int bcol = (ks << 4) + ((mat & 1) << 3);
                uint32_t bh[4];
                ldsm4(bh, sbase + C::offB(cur) +
                      swz128((uint32_t)(brow * 128 + bcol * 2)));
                mma16816(acc[nt2 * 2], ah, bh[0], bh[1]);
                mma16816(acc[nt2 * 2 + 1], ah, bh[2], bh[3]);
            }
        }
        if (more) {
#pragma unroll
            for (int t = 0; t < 8; t++) {
                int idx = tid + t * 256;
                int row = idx >> 4, q = idx & 15;
                int j = (ch + 1) * C::KC + q * 4;
                int k = j / FIN;
                convA(cur ^ 1, idx, av[t], sD[row * KNBR + k]);
            }
            asm volatile("cp.async.wait_group 0;");
            __syncthreads();
        }
    }

    const int g = lane >> 2, tig = lane & 3;
    const int row0 = n0 + mrow + g;
#pragma unroll
    for (int nt = 0; nt < FOUT / 8; nt++) {
        int col = nt * 8 + tig * 2;
        float b0 = bg[col], b1 = bg[col + 1];
        *reinterpret_cast<uint32_t*>(out + (size_t)row0 * FOUT + col) =
            pack_h2(acc[nt][0] + b0, acc[nt][1] + b1);
        *reinterpret_cast<uint32_t*>(out + (size_t)(row0 + 8) * FOUT + col) =
            pack_h2(acc[nt][2] + b0, acc[nt][3] + b1);
    }
}

// ============ combine: out[n] = b2 + sum_k invd[n,k] * Z16[nbr[n,k], k*16:] =
__global__ void __launch_bounds__(256)
combine2_kernel(const int* __restrict__ nbr, const __half* __restrict__ Z,
                const float* __restrict__ b2, float* __restrict__ out) {
    int n = blockIdx.x * 256 + threadIdx.x;
    const int4* nb = reinterpret_cast<const int4*>(nbr + (size_t)n * 8);
    int4 nb0 = nb[0], nb1 = nb[1];
    const float4* iv = reinterpret_cast<const float4*>(g_invd + (size_t)n * 8);
    float4 s0 = iv[0], s1 = iv[1];
    int idx[8] = {nb0.x, nb0.y, nb0.z, nb0.w, nb1.x, nb1.y, nb1.z, nb1.w};
    float sc[8] = {s0.x, s0.y, s0.z, s0.w, s1.x, s1.y, s1.z, s1.w};
    float acc[16];
#pragma unroll
    for (int q = 0; q < 4; q++) {
        float4 b = reinterpret_cast<const float4*>(b2)[q];
        acc[q * 4 + 0] = b.x; acc[q * 4 + 1] = b.y;
        acc[q * 4 + 2] = b.z; acc[q * 4 + 3] = b.w;
    }
#pragma unroll
    for (int k = 0; k < 8; k++) {
        const uint4* zp = reinterpret_cast<const uint4*>(
            Z + (size_t)idx[k] * 128 + k * 16);
        uint4 za = zp[0], zb = zp[1];
        const uint32_t zw[8] = {za.x, za.y, za.z, za.w, zb.x, zb.y, zb.z, zb.w};
        float s = sc[k];
#pragma unroll
        for (int q = 0; q < 8; q++) {
            float2 z = __half22float2(*reinterpret_cast<const __half2*>(&zw[q]));
            acc[q * 2 + 0] += s * z.x;
            acc[q * 2 + 1] += s * z.y;
        }
    }
    float4* op = reinterpret_cast<float4*>(out + (size_t)n * 16);
#pragma unroll
    for (int q = 0; q < 4; q++)
        op[q] = make_float4(acc[q * 4], acc[q * 4 + 1], acc[q * 4 + 2], acc[q * 4 + 3]);
}

// ---------------- host launch ----------------
extern "C" void kernel_launch(void* const* d_in, const int* in_sizes, int n_in,
                              void* d_out, int out_size) {
    const float* h   = (const float*)d_in[0];
    const float* pos = (const float*)d_in[1];
    const int*   nbr = (const int*)d_in[2];
    const float* W0  = (const float*)d_in[3];
    const float* b0  = (const float*)d_in[4];
    const float* W1  = (const float*)d_in[5];
    const float* b1  = (const float*)d_in[6];
    const float* W2  = (const float*)d_in[7];
    const float* b2  = (const float*)d_in[8];
    float* out = (float*)d_out;

    __half *h1, *z, *wt0, *wt1, *wt2c;
    cudaGetSymbolAddress((void**)&h1, g_h1);
    cudaGetSymbolAddress((void**)&z, g_z);
    cudaGetSymbolAddress((void**)&wt0, g_wt0h);
    cudaGetSymbolAddress((void**)&wt1, g_wt1h);
    cudaGetSymbolAddress((void**)&wt2c, g_wt2c);

    constexpr int SM0 = P0::SMEM_BYTES;         // 73728
    constexpr int SM1 = P1::SMEM_BYTES;         // 106496

    cudaFuncSetAttribute((const void*)layer0_kernel,
                         cudaFuncAttributeMaxDynamicSharedMemorySize, SM0);
    cudaFuncSetAttribute((const void*)layer1_kernel,
                         cudaFuncAttributeMaxDynamicSharedMemorySize, SM1);

    prep_kernel<<<8832, 256>>>(pos, nbr, W0, W1, W2);
    layer0_kernel<<<NNODES / 128, 256, SM0>>>(h, nbr, wt0, b0, h1);
    layer1_kernel<<<NNODES / 128, 256, SM1>>>(h1, nbr, wt1, wt2c, b1, z);
    combine2_kernel<<<NNODES / 256, 256>>>(nbr, z, b2, out);
}